// round 3
// baseline (speedup 1.0000x reference)
#include <cuda_runtime.h>
#include <cuda_bf16.h>

#define FULLMASK 0xffffffffu

namespace {
constexpr int B = 64;
constexpr int T = 32768;
constexpr int R = 16;
constexpr int SPW = 2;          // samples per warp (software-pipelined)
constexpr int UNROLL = 4;
}

// Scratch: hidden states for all steps, layout [B][T][R] (y-projection in pass 2).
__device__ float g_hs[(size_t)B * T * R];   // 128 MiB

__device__ __forceinline__ float lrelu(float v) { return v >= 0.f ? v : 0.1f * v; }
__device__ __forceinline__ float tanh_fast(float v) {
    float r;
    asm("tanh.approx.f32 %0, %1;" : "=f"(r) : "f"(v));
    return r;
}

__global__ void __launch_bounds__(32, 1) hypergru_rnn_kernel(
    const float* __restrict__ x,      // [B,1,T]
    const float* __restrict__ c,      // [B,8]
    const float* __restrict__ h0,     // [1,B,R]
    const float* __restrict__ mlp_w1, const float* __restrict__ mlp_b1,
    const float* __restrict__ mlp_w2, const float* __restrict__ mlp_b2,
    const float* __restrict__ pih_w,  const float* __restrict__ pih_b,
    const float* __restrict__ phh_w,  const float* __restrict__ phh_b,
    const float* __restrict__ pbih_w, const float* __restrict__ pbih_b,
    const float* __restrict__ pbhh_w, const float* __restrict__ pbhh_b,
    float* __restrict__ out)          // only h_last region written here
{
    const int lane = threadIdx.x;
    const int j    = lane & 15;          // hidden unit owned by this lane
    const int koff = (lane >> 4) * 8;    // lower half sums k=0..7, upper k=8..15
    const int b0   = blockIdx.x * SPW;

    // Per-sample recurrent constants.
    // r/i-gate hh weights pre-halved (sigmoid via 0.5*tanh(v/2)+0.5);
    // r/i input weights/biases pre-quartered (seeded into BOTH k-halves, xor-combine doubles).
    float whr_h[SPW][8], whi_h[SPW][8], whn[SPW][8];
    float wih_r_q[SPW], wih_i_q[SPW], cbr_q[SPW], cbi_q[SPW];
    float wih_n[SPW], bih_n[SPW], bhh_n_h[SPW];
    float h[SPW];

#pragma unroll
    for (int s = 0; s < SPW; ++s) {
        const int b = b0 + s;
        // ---------------- hypernetwork prologue ----------------
        float cv[8];
#pragma unroll
        for (int k = 0; k < 8; ++k) cv[k] = c[b * 8 + k];
        float w1[8];
#pragma unroll
        for (int m = 0; m < 8; ++m) {
            float a = mlp_b1[m];
#pragma unroll
            for (int k = 0; k < 8; ++k) a = fmaf(cv[k], mlp_w1[m * 8 + k], a);
            w1[m] = lrelu(a);
        }
        float w2[8];
#pragma unroll
        for (int m = 0; m < 8; ++m) {
            float a = mlp_b2[m];
#pragma unroll
            for (int k = 0; k < 8; ++k) a = fmaf(w1[k], mlp_w2[m * 8 + k], a);
            w2[m] = lrelu(a);
        }
        auto proj8 = [&](const float* __restrict__ wrow, float bias) -> float {
            float a = bias;
#pragma unroll
            for (int k = 0; k < 8; ++k) a = fmaf(w2[k], wrow[k], a);
            return a;
        };

#pragma unroll
        for (int k = 0; k < 8; ++k) {
            const int kk = k + koff;
            whr_h[s][k] = 0.5f * proj8(phh_w + (size_t)(kk * 48 + j) * 8,      phh_b[kk * 48 + j]);
            whi_h[s][k] = 0.5f * proj8(phh_w + (size_t)(kk * 48 + 16 + j) * 8, phh_b[kk * 48 + 16 + j]);
            whn[s][k]   =        proj8(phh_w + (size_t)(kk * 48 + 32 + j) * 8, phh_b[kk * 48 + 32 + j]);
        }
        const float bih_r = proj8(pbih_w + (size_t)j * 8,        pbih_b[j]);
        const float bih_i = proj8(pbih_w + (size_t)(16 + j) * 8, pbih_b[16 + j]);
        const float bhh_r = proj8(pbhh_w + (size_t)j * 8,        pbhh_b[j]);
        const float bhh_i = proj8(pbhh_w + (size_t)(16 + j) * 8, pbhh_b[16 + j]);

        wih_r_q[s] = 0.25f * proj8(pih_w + (size_t)j * 8,        pih_b[j]);
        wih_i_q[s] = 0.25f * proj8(pih_w + (size_t)(16 + j) * 8, pih_b[16 + j]);
        wih_n[s]   =         proj8(pih_w + (size_t)(32 + j) * 8, pih_b[32 + j]);
        cbr_q[s]   = 0.25f * (bih_r + bhh_r);
        cbi_q[s]   = 0.25f * (bih_i + bhh_i);
        bih_n[s]   = proj8(pbih_w + (size_t)(32 + j) * 8, pbih_b[32 + j]);
        bhh_n_h[s] = 0.5f * proj8(pbhh_w + (size_t)(32 + j) * 8, pbhh_b[32 + j]);

        h[s] = h0[b * R + j];
    }

    // Per-lane hs store pointer: lanes 0-15 store sample 0, lanes 16-31 sample 1.
    const int smine = lane >> 4;
    float* __restrict__ hsp = g_hs + (size_t)(b0 + smine) * T * R + j;

    const float* __restrict__ xp0 = x + (size_t)b0 * T;
    const float* __restrict__ xp1 = x + (size_t)(b0 + 1) * T;

    float xcur[SPW];
    xcur[0] = xp0[lane];
    xcur[1] = xp1[lane];

    for (int t0 = 0; t0 < T; t0 += 32) {
        float xnext0 = (t0 + 32 < T) ? xp0[t0 + 32 + lane] : 0.f;
        float xnext1 = (t0 + 32 < T) ? xp1[t0 + 32 + lane] : 0.f;
        for (int tb = 0; tb < 32; tb += UNROLL) {
#pragma unroll
            for (int tt = 0; tt < UNROLL; ++tt) {
                const int ti = tb + tt;
                float hnew[SPW];
#pragma unroll
                for (int s = 0; s < SPW; ++s) {
                    const float xt = __shfl_sync(FULLMASK, xcur[s], ti, 32);
                    // gather this half's 8 h-values
                    float hrv[8];
#pragma unroll
                    for (int k = 0; k < 8; ++k)
                        hrv[k] = __shfl_sync(FULLMASK, h[s], k + koff, 16);

                    // seeds (per-half quarter-scaled input terms; xor-combine doubles them)
                    const float seed_r = fmaf(xt, wih_r_q[s], cbr_q[s]);
                    const float seed_i = fmaf(xt, wih_i_q[s], cbi_q[s]);

                    float r0 = fmaf(hrv[0], whr_h[s][0], seed_r);
                    float i0 = fmaf(hrv[0], whi_h[s][0], seed_i);
                    float n0 = fmaf(hrv[0], whn[s][0],   bhh_n_h[s]);
                    float r1 = hrv[4] * whr_h[s][4];
                    float i1 = hrv[4] * whi_h[s][4];
                    float n1 = hrv[4] * whn[s][4];
#pragma unroll
                    for (int k = 1; k < 4; ++k) {
                        r0 = fmaf(hrv[k],     whr_h[s][k],     r0);
                        r1 = fmaf(hrv[k + 4], whr_h[s][k + 4], r1);
                        i0 = fmaf(hrv[k],     whi_h[s][k],     i0);
                        i1 = fmaf(hrv[k + 4], whi_h[s][k + 4], i1);
                        n0 = fmaf(hrv[k],     whn[s][k],       n0);
                        n1 = fmaf(hrv[k + 4], whn[s][k + 4],   n1);
                    }
                    const float rp = r0 + r1, ip = i0 + i1, np = n0 + n1;
                    // combine the two k-halves: every lane gets full (pre-scaled) sums
                    const float rf = rp + __shfl_xor_sync(FULLMASK, rp, 16);
                    const float iff = ip + __shfl_xor_sync(FULLMASK, ip, 16);
                    const float hn = np + __shfl_xor_sync(FULLMASK, np, 16); // = full n hh-sum + bhh_n

                    const float i_n = fmaf(xt, wih_n[s], bih_n[s]);
                    const float inp = fmaf(0.5f, hn, i_n);   // i_n + 0.5*hn
                    const float hnh = 0.5f * hn;

                    const float tr = tanh_fast(rf);          // = 2*rg - 1
                    const float tiv = tanh_fast(iff);
                    const float ng = tanh_fast(fmaf(tr, hnh, inp)); // tanh(i_n + rg*hn)
                    const float ig = fmaf(tiv, 0.5f, 0.5f);

                    hnew[s] = fmaf(ig, h[s] - ng, ng);
                    h[s] = hnew[s];
                }
                // one store covers both samples (lane<16 -> s0, lane>=16 -> s1)
                hsp[(size_t)(t0 + ti) * R] = hnew[smine];
            }
        }
        xcur[0] = xnext0;
        xcur[1] = xnext1;
    }

#pragma unroll
    for (int s = 0; s < SPW; ++s)
        if ((lane >> 4) == 0)   // lanes 0-15 hold valid replicas for both samples
            out[(size_t)B * T + (b0 + s) * R + j] = h[s];
}

// Second pass: y[b,t] = dot(hs[b,t,:], out_w) + out_b  (bandwidth-bound, parallel)
__global__ void __launch_bounds__(256) out_proj_kernel(
    const float* __restrict__ out_w, const float* __restrict__ out_b,
    float* __restrict__ out)
{
    const int idx = blockIdx.x * 256 + threadIdx.x;   // idx = b*T + t
    const float4* __restrict__ hp = reinterpret_cast<const float4*>(g_hs) + (size_t)idx * 4;
    float4 v0 = hp[0], v1 = hp[1], v2 = hp[2], v3 = hp[3];
    const float4* __restrict__ wp = reinterpret_cast<const float4*>(out_w);
    float4 w0 = __ldg(wp), w1 = __ldg(wp + 1), w2 = __ldg(wp + 2), w3 = __ldg(wp + 3);

    float a = __ldg(out_b);
    a = fmaf(v0.x, w0.x, a); a = fmaf(v0.y, w0.y, a); a = fmaf(v0.z, w0.z, a); a = fmaf(v0.w, w0.w, a);
    a = fmaf(v1.x, w1.x, a); a = fmaf(v1.y, w1.y, a); a = fmaf(v1.z, w1.z, a); a = fmaf(v1.w, w1.w, a);
    a = fmaf(v2.x, w2.x, a); a = fmaf(v2.y, w2.y, a); a = fmaf(v2.z, w2.z, a); a = fmaf(v2.w, w2.w, a);
    a = fmaf(v3.x, w3.x, a); a = fmaf(v3.y, w3.y, a); a = fmaf(v3.z, w3.z, a); a = fmaf(v3.w, w3.w, a);
    out[idx] = a;
}

extern "C" void kernel_launch(void* const* d_in, const int* in_sizes, int n_in,
                              void* d_out, int out_size) {
    (void)in_sizes; (void)n_in; (void)out_size;
    hypergru_rnn_kernel<<<B / SPW, 32>>>(
        (const float*)d_in[0],  (const float*)d_in[1],  (const float*)d_in[2],
        (const float*)d_in[3],  (const float*)d_in[4],  (const float*)d_in[5],
        (const float*)d_in[6],  (const float*)d_in[7],  (const float*)d_in[8],
        (const float*)d_in[9],  (const float*)d_in[10], (const float*)d_in[11],
        (const float*)d_in[12], (const float*)d_in[13], (const float*)d_in[14],
        (float*)d_out);
    out_proj_kernel<<<(B * T) / 256, 256>>>(
        (const float*)d_in[15], (const float*)d_in[16], (float*)d_out);
}

// round 4
// speedup vs baseline: 1.0715x; 1.0715x over previous
#include <cuda_runtime.h>
#include <cuda_bf16.h>

#define FULLMASK 0xffffffffu

namespace {
constexpr int B = 64;
constexpr int T = 32768;
constexpr int R = 16;
}

// Scratch: hidden states for all steps, layout [B][T][R] (y-projection in pass 2).
__device__ float g_hs[(size_t)B * T * R];   // 128 MiB

__device__ __forceinline__ float lrelu(float v) { return v >= 0.f ? v : 0.1f * v; }
__device__ __forceinline__ float tanh_fast(float v) {
    float r;
    asm("tanh.approx.f32 %0, %1;" : "=f"(r) : "f"(v));
    return r;
}
__device__ __forceinline__ unsigned long long pack2(float lo, float hi) {
    unsigned long long r;
    asm("mov.b64 %0, {%1, %2};" : "=l"(r) : "f"(lo), "f"(hi));
    return r;
}
__device__ __forceinline__ void unpack2(unsigned long long v, float& lo, float& hi) {
    asm("mov.b64 {%0, %1}, %2;" : "=f"(lo), "=f"(hi) : "l"(v));
}
__device__ __forceinline__ unsigned long long fma2(unsigned long long a,
                                                   unsigned long long b,
                                                   unsigned long long c) {
    unsigned long long d;
    asm("fma.rn.f32x2 %0, %1, %2, %3;" : "=l"(d) : "l"(a), "l"(b), "l"(c));
    return d;
}
__device__ __forceinline__ unsigned long long mul2(unsigned long long a,
                                                   unsigned long long b) {
    unsigned long long d;
    asm("mul.rn.f32x2 %0, %1, %2;" : "=l"(d) : "l"(a), "l"(b));
    return d;
}
__device__ __forceinline__ unsigned long long add2(unsigned long long a,
                                                   unsigned long long b) {
    unsigned long long d;
    asm("add.rn.f32x2 %0, %1, %2;" : "=l"(d) : "l"(a), "l"(b));
    return d;
}

// One warp = 2 samples, SIMD: lanes 0-15 -> sample b0, lanes 16-31 -> sample b0+1.
// Lane (g, j) owns hidden unit j of its sample. All shuffles width 16.
__global__ void __launch_bounds__(32, 1) hypergru_rnn_kernel(
    const float* __restrict__ x,      // [B,1,T]
    const float* __restrict__ c,      // [B,8]
    const float* __restrict__ h0,     // [1,B,R]
    const float* __restrict__ mlp_w1, const float* __restrict__ mlp_b1,
    const float* __restrict__ mlp_w2, const float* __restrict__ mlp_b2,
    const float* __restrict__ pih_w,  const float* __restrict__ pih_b,
    const float* __restrict__ phh_w,  const float* __restrict__ phh_b,
    const float* __restrict__ pbih_w, const float* __restrict__ pbih_b,
    const float* __restrict__ pbhh_w, const float* __restrict__ pbhh_b,
    float* __restrict__ out)          // only h_last region written here
{
    const int lane = threadIdx.x;
    const int j    = lane & 15;               // hidden unit owned by this lane
    const int b    = blockIdx.x * 2 + (lane >> 4);

    // ---------------- hypernetwork prologue (per-lane, for its sample) -------
    float cv[8];
#pragma unroll
    for (int k = 0; k < 8; ++k) cv[k] = c[b * 8 + k];
    float w1[8];
#pragma unroll
    for (int m = 0; m < 8; ++m) {
        float a = mlp_b1[m];
#pragma unroll
        for (int k = 0; k < 8; ++k) a = fmaf(cv[k], mlp_w1[m * 8 + k], a);
        w1[m] = lrelu(a);
    }
    float w2[8];
#pragma unroll
    for (int m = 0; m < 8; ++m) {
        float a = mlp_b2[m];
#pragma unroll
        for (int k = 0; k < 8; ++k) a = fmaf(w1[k], mlp_w2[m * 8 + k], a);
        w2[m] = lrelu(a);
    }
    auto proj8 = [&](const float* __restrict__ wrow, float bias) -> float {
        float a = bias;
#pragma unroll
        for (int k = 0; k < 8; ++k) a = fmaf(w2[k], wrow[k], a);
        return a;
    };

    // Recurrent hh weights as packed pairs over k (source unit): pair m = {k=2m, k=2m+1}.
    // r/i gate weights pre-halved: sigmoid computed as 0.5*tanh(v/2)+0.5.
    unsigned long long wr2[8], wi2[8], wn2[8];
#pragma unroll
    for (int m = 0; m < 8; ++m) {
        const int k0 = 2 * m, k1 = 2 * m + 1;
        wr2[m] = pack2(
            0.5f * proj8(phh_w + (size_t)(k0 * 48 + j) * 8, phh_b[k0 * 48 + j]),
            0.5f * proj8(phh_w + (size_t)(k1 * 48 + j) * 8, phh_b[k1 * 48 + j]));
        wi2[m] = pack2(
            0.5f * proj8(phh_w + (size_t)(k0 * 48 + 16 + j) * 8, phh_b[k0 * 48 + 16 + j]),
            0.5f * proj8(phh_w + (size_t)(k1 * 48 + 16 + j) * 8, phh_b[k1 * 48 + 16 + j]));
        wn2[m] = pack2(
            proj8(phh_w + (size_t)(k0 * 48 + 32 + j) * 8, phh_b[k0 * 48 + 32 + j]),
            proj8(phh_w + (size_t)(k1 * 48 + 32 + j) * 8, phh_b[k1 * 48 + 32 + j]));
    }

    const float wih_r_h = 0.5f * proj8(pih_w + (size_t)j * 8,        pih_b[j]);
    const float wih_i_h = 0.5f * proj8(pih_w + (size_t)(16 + j) * 8, pih_b[16 + j]);
    const float wih_n   =        proj8(pih_w + (size_t)(32 + j) * 8, pih_b[32 + j]);

    const float bih_r = proj8(pbih_w + (size_t)j * 8,        pbih_b[j]);
    const float bih_i = proj8(pbih_w + (size_t)(16 + j) * 8, pbih_b[16 + j]);
    const float bih_n = proj8(pbih_w + (size_t)(32 + j) * 8, pbih_b[32 + j]);
    const float bhh_r = proj8(pbhh_w + (size_t)j * 8,        pbhh_b[j]);
    const float bhh_i = proj8(pbhh_w + (size_t)(16 + j) * 8, pbhh_b[16 + j]);
    const float bhh_n = proj8(pbhh_w + (size_t)(32 + j) * 8, pbhh_b[32 + j]);

    const float cbr_h = 0.5f * (bih_r + bhh_r);
    const float cbi_h = 0.5f * (bih_i + bhh_i);

    // ---------------- recurrence ----------------
    float h = h0[b * R + j];
    const float* __restrict__ xp = x + (size_t)b * T;
    float* __restrict__ hsp = g_hs + (size_t)b * T * R + j;

    float xq = xp[j];   // 16 timesteps staged per lane (width-16 group)
    for (int t0 = 0; t0 < T; t0 += 16) {
        const float xnext = (t0 + 16 < T) ? xp[t0 + 16 + j] : 0.f;   // prefetch
        for (int tb = 0; tb < 16; tb += 8) {                          // small body (I$)
#pragma unroll
            for (int tt = 0; tt < 8; ++tt) {
                const int ti = tb + tt;
                const float xt = __shfl_sync(FULLMASK, xq, ti, 16);

                // gather full h of this sample as 8 packed pairs
                unsigned long long hp[8];
#pragma unroll
                for (int m = 0; m < 8; ++m) {
                    const float lo = __shfl_sync(FULLMASK, h, 2 * m,     16);
                    const float hi = __shfl_sync(FULLMASK, h, 2 * m + 1, 16);
                    hp[m] = pack2(lo, hi);
                }

                // seeds folded into chain A (lo slot)
                const unsigned long long seedR = pack2(fmaf(xt, wih_r_h, cbr_h), 0.f);
                const unsigned long long seedI = pack2(fmaf(xt, wih_i_h, cbi_h), 0.f);
                const unsigned long long seedN = pack2(bhh_n, 0.f);

                unsigned long long aR = fma2(hp[0], wr2[0], seedR);
                unsigned long long aI = fma2(hp[0], wi2[0], seedI);
                unsigned long long aN = fma2(hp[0], wn2[0], seedN);
                unsigned long long bR = mul2(hp[4], wr2[4]);
                unsigned long long bI = mul2(hp[4], wi2[4]);
                unsigned long long bN = mul2(hp[4], wn2[4]);
#pragma unroll
                for (int m = 1; m < 4; ++m) {
                    aR = fma2(hp[m], wr2[m], aR);   bR = fma2(hp[m + 4], wr2[m + 4], bR);
                    aI = fma2(hp[m], wi2[m], aI);   bI = fma2(hp[m + 4], wi2[m + 4], bI);
                    aN = fma2(hp[m], wn2[m], aN);   bN = fma2(hp[m + 4], wn2[m + 4], bN);
                }
                float rl, rh, il, ih2, nl, nh;
                unpack2(add2(aR, bR), rl, rh);
                unpack2(add2(aI, bI), il, ih2);
                unpack2(add2(aN, bN), nl, nh);
                const float rf = rl + rh;           // 0.5*(pre-activation of r)
                const float iv = il + ih2;          // 0.5*(pre-activation of i)
                const float hn = nl + nh;           // full n hh-sum + bhh_n

                const float i_n = fmaf(xt, wih_n, bih_n);
                const float inp = fmaf(0.5f, hn, i_n);          // i_n + 0.5*hn
                const float tr  = tanh_fast(rf);                // = 2*rg - 1
                const float ng  = tanh_fast(fmaf(tr, 0.5f * hn, inp));
                const float ig  = fmaf(tanh_fast(iv), 0.5f, 0.5f);

                h = fmaf(ig, h - ng, ng);           // hy = ng + ig*(h - ng)
                hsp[(size_t)(t0 + ti) * R] = h;
            }
        }
        xq = xnext;
    }

    out[(size_t)B * T + b * R + j] = h;
}

// Second pass: y[b,t] = dot(hs[b,t,:], out_w) + out_b  (bandwidth-bound, parallel)
__global__ void __launch_bounds__(256) out_proj_kernel(
    const float* __restrict__ out_w, const float* __restrict__ out_b,
    float* __restrict__ out)
{
    const int idx = blockIdx.x * 256 + threadIdx.x;   // idx = b*T + t
    const float4* __restrict__ hp = reinterpret_cast<const float4*>(g_hs) + (size_t)idx * 4;
    float4 v0 = hp[0], v1 = hp[1], v2 = hp[2], v3 = hp[3];
    const float4* __restrict__ wp = reinterpret_cast<const float4*>(out_w);
    float4 w0 = __ldg(wp), w1 = __ldg(wp + 1), w2 = __ldg(wp + 2), w3 = __ldg(wp + 3);

    float a = __ldg(out_b);
    a = fmaf(v0.x, w0.x, a); a = fmaf(v0.y, w0.y, a); a = fmaf(v0.z, w0.z, a); a = fmaf(v0.w, w0.w, a);
    a = fmaf(v1.x, w1.x, a); a = fmaf(v1.y, w1.y, a); a = fmaf(v1.z, w1.z, a); a = fmaf(v1.w, w1.w, a);
    a = fmaf(v2.x, w2.x, a); a = fmaf(v2.y, w2.y, a); a = fmaf(v2.z, w2.z, a); a = fmaf(v2.w, w2.w, a);
    a = fmaf(v3.x, w3.x, a); a = fmaf(v3.y, w3.y, a); a = fmaf(v3.z, w3.z, a); a = fmaf(v3.w, w3.w, a);
    out[idx] = a;
}

extern "C" void kernel_launch(void* const* d_in, const int* in_sizes, int n_in,
                              void* d_out, int out_size) {
    (void)in_sizes; (void)n_in; (void)out_size;
    hypergru_rnn_kernel<<<B / 2, 32>>>(
        (const float*)d_in[0],  (const float*)d_in[1],  (const float*)d_in[2],
        (const float*)d_in[3],  (const float*)d_in[4],  (const float*)d_in[5],
        (const float*)d_in[6],  (const float*)d_in[7],  (const float*)d_in[8],
        (const float*)d_in[9],  (const float*)d_in[10], (const float*)d_in[11],
        (const float*)d_in[12], (const float*)d_in[13], (const float*)d_in[14],
        (float*)d_out);
    out_proj_kernel<<<(B * T) / 256, 256>>>(
        (const float*)d_in[15], (const float*)d_in[16], (float*)d_out);
}

// round 5
// speedup vs baseline: 1.1574x; 1.0802x over previous
#include <cuda_runtime.h>
#include <cuda_bf16.h>

#define FULLMASK 0xffffffffu

namespace {
constexpr int B = 64;
constexpr int T = 32768;
constexpr int R = 16;
}

// Scratch: hidden states, TRANSPOSED layout: row (b*16 + j) holds h_j over time.
__device__ float g_hs[(size_t)B * R * T];   // 128 MiB

__device__ __forceinline__ float lrelu(float v) { return v >= 0.f ? v : 0.1f * v; }
__device__ __forceinline__ float tanh_fast(float v) {
    float r;
    asm("tanh.approx.f32 %0, %1;" : "=f"(r) : "f"(v));
    return r;
}

// One warp per sample. Lane (g, j): g = lane>>4, j = lane&15.
// Lane owns hidden unit j; half g sums k = 8g..8g+7 of each gate (split-k),
// halves combined with one shfl_xor(16) per gate.
__global__ void __launch_bounds__(32, 1) hypergru_rnn_kernel(
    const float* __restrict__ x,      // [B,1,T]
    const float* __restrict__ c,      // [B,8]
    const float* __restrict__ h0,     // [1,B,R]
    const float* __restrict__ mlp_w1, const float* __restrict__ mlp_b1,
    const float* __restrict__ mlp_w2, const float* __restrict__ mlp_b2,
    const float* __restrict__ pih_w,  const float* __restrict__ pih_b,
    const float* __restrict__ phh_w,  const float* __restrict__ phh_b,
    const float* __restrict__ pbih_w, const float* __restrict__ pbih_b,
    const float* __restrict__ pbhh_w, const float* __restrict__ pbhh_b,
    float* __restrict__ out)          // only h_last region written here
{
    const int b    = blockIdx.x;
    const int lane = threadIdx.x;
    const int j    = lane & 15;
    const int koff = (lane >> 4) * 8;

    // ---------------- hypernetwork prologue ----------------
    float cv[8];
#pragma unroll
    for (int k = 0; k < 8; ++k) cv[k] = c[b * 8 + k];
    float w1[8];
#pragma unroll
    for (int m = 0; m < 8; ++m) {
        float a = mlp_b1[m];
#pragma unroll
        for (int k = 0; k < 8; ++k) a = fmaf(cv[k], mlp_w1[m * 8 + k], a);
        w1[m] = lrelu(a);
    }
    float w2[8];
#pragma unroll
    for (int m = 0; m < 8; ++m) {
        float a = mlp_b2[m];
#pragma unroll
        for (int k = 0; k < 8; ++k) a = fmaf(w1[k], mlp_w2[m * 8 + k], a);
        w2[m] = lrelu(a);
    }
    auto proj8 = [&](const float* __restrict__ wrow, float bias) -> float {
        float a = bias;
#pragma unroll
        for (int k = 0; k < 8; ++k) a = fmaf(w2[k], wrow[k], a);
        return a;
    };

    // Recurrent weights for this lane's 8 k-terms.
    // r/i weights pre-halved (sigmoid via 0.5*tanh(v/2)+0.5).
    float whr_h[8], whi_h[8], whn[8];
#pragma unroll
    for (int k = 0; k < 8; ++k) {
        const int kk = k + koff;
        whr_h[k] = 0.5f * proj8(phh_w + (size_t)(kk * 48 + j) * 8,      phh_b[kk * 48 + j]);
        whi_h[k] = 0.5f * proj8(phh_w + (size_t)(kk * 48 + 16 + j) * 8, phh_b[kk * 48 + 16 + j]);
        whn[k]   =        proj8(phh_w + (size_t)(kk * 48 + 32 + j) * 8, phh_b[kk * 48 + 32 + j]);
    }
    const float bih_r = proj8(pbih_w + (size_t)j * 8,        pbih_b[j]);
    const float bih_i = proj8(pbih_w + (size_t)(16 + j) * 8, pbih_b[16 + j]);
    const float bhh_r = proj8(pbhh_w + (size_t)j * 8,        pbhh_b[j]);
    const float bhh_i = proj8(pbhh_w + (size_t)(16 + j) * 8, pbhh_b[16 + j]);

    // quarter-scaled seeds: each half seeds 0.25*(input term); xor-combine doubles.
    const float wih_r_q = 0.25f * proj8(pih_w + (size_t)j * 8,        pih_b[j]);
    const float wih_i_q = 0.25f * proj8(pih_w + (size_t)(16 + j) * 8, pih_b[16 + j]);
    const float wih_n   =         proj8(pih_w + (size_t)(32 + j) * 8, pih_b[32 + j]);
    const float cbr_q   = 0.25f * (bih_r + bhh_r);
    const float cbi_q   = 0.25f * (bih_i + bhh_i);
    const float bih_n   = proj8(pbih_w + (size_t)(32 + j) * 8, pbih_b[32 + j]);
    const float bhh_n_h = 0.5f * proj8(pbhh_w + (size_t)(32 + j) * 8, pbhh_b[32 + j]);

    // ---------------- recurrence ----------------
    float h = h0[b * R + j];
    const float* __restrict__ xp = x + (size_t)b * T;
    float* __restrict__ hsp = g_hs + (size_t)(b * R + j) * T;   // this lane's row

    float xq = xp[lane];   // 32 timesteps staged per lane
    for (int t0 = 0; t0 < T; t0 += 32) {
        const float xnext = (t0 + 32 < T) ? xp[t0 + 32 + lane] : 0.f;   // prefetch
#pragma unroll 1
        for (int q = 0; q < 8; ++q) {                 // 4-step hot body fits L0 I$
            float4 vbuf;
#pragma unroll
            for (int tt = 0; tt < 4; ++tt) {
                const int ti = q * 4 + tt;
                const float xt = __shfl_sync(FULLMASK, xq, ti, 32);

                // gather this half's 8 h-values
                float hrv[8];
#pragma unroll
                for (int k = 0; k < 8; ++k)
                    hrv[k] = __shfl_sync(FULLMASK, h, k + koff, 16);

                const float seed_r = fmaf(xt, wih_r_q, cbr_q);
                const float seed_i = fmaf(xt, wih_i_q, cbi_q);

                float r0 = fmaf(hrv[0], whr_h[0], seed_r);
                float i0 = fmaf(hrv[0], whi_h[0], seed_i);
                float n0 = fmaf(hrv[0], whn[0],   bhh_n_h);
                float r1 = hrv[4] * whr_h[4];
                float i1 = hrv[4] * whi_h[4];
                float n1 = hrv[4] * whn[4];
#pragma unroll
                for (int k = 1; k < 4; ++k) {
                    r0 = fmaf(hrv[k],     whr_h[k],     r0);
                    r1 = fmaf(hrv[k + 4], whr_h[k + 4], r1);
                    i0 = fmaf(hrv[k],     whi_h[k],     i0);
                    i1 = fmaf(hrv[k + 4], whi_h[k + 4], i1);
                    n0 = fmaf(hrv[k],     whn[k],       n0);
                    n1 = fmaf(hrv[k + 4], whn[k + 4],   n1);
                }
                const float rp = r0 + r1, ip = i0 + i1, np = n0 + n1;
                const float rf = rp + __shfl_xor_sync(FULLMASK, rp, 16);  // 0.5*preact_r
                const float iv = ip + __shfl_xor_sync(FULLMASK, ip, 16);  // 0.5*preact_i
                const float hn = np + __shfl_xor_sync(FULLMASK, np, 16);  // full n hh-sum + bhh_n

                const float i_n = fmaf(xt, wih_n, bih_n);
                const float inp = fmaf(0.5f, hn, i_n);            // i_n + 0.5*hn
                const float tr  = tanh_fast(rf);                  // = 2*rg - 1
                const float ng  = tanh_fast(fmaf(tr, 0.5f * hn, inp));
                const float ig  = fmaf(tanh_fast(iv), 0.5f, 0.5f);

                h = fmaf(ig, h - ng, ng);
                (&vbuf.x)[tt] = h;
            }
            if (lane < 16)    // halves are replicas; one writes
                *reinterpret_cast<float4*>(hsp + t0 + q * 4) = vbuf;
        }
        xq = xnext;
    }

    if (lane < 16) out[(size_t)B * T + b * R + j] = h;
}

// Pass 2: y[b,t] = sum_j hs[b][j][t]*w[j] + ob.  Transposed-layout reader,
// each thread produces 4 consecutive t via float4 loads per row. BW-bound.
__global__ void __launch_bounds__(256) out_proj_kernel(
    const float* __restrict__ out_w, const float* __restrict__ out_b,
    float* __restrict__ out)
{
    const int tid = blockIdx.x * 256 + threadIdx.x;    // B*T/4 threads
    const int b   = tid / (T / 4);
    const int t4  = tid - b * (T / 4);
    const float* __restrict__ base = g_hs + (size_t)b * R * T + (size_t)t4 * 4;

    float w[16];
#pragma unroll
    for (int k = 0; k < 16; ++k) w[k] = __ldg(out_w + k);
    const float ob = __ldg(out_b);

    float a0 = ob, a1 = ob, a2 = ob, a3 = ob;
#pragma unroll
    for (int k = 0; k < 16; ++k) {
        const float4 v = *reinterpret_cast<const float4*>(base + (size_t)k * T);
        a0 = fmaf(v.x, w[k], a0);
        a1 = fmaf(v.y, w[k], a1);
        a2 = fmaf(v.z, w[k], a2);
        a3 = fmaf(v.w, w[k], a3);
    }
    float4 r = make_float4(a0, a1, a2, a3);
    *reinterpret_cast<float4*>(out + (size_t)b * T + (size_t)t4 * 4) = r;
}

extern "C" void kernel_launch(void* const* d_in, const int* in_sizes, int n_in,
                              void* d_out, int out_size) {
    (void)in_sizes; (void)n_in; (void)out_size;
    hypergru_rnn_kernel<<<B, 32>>>(
        (const float*)d_in[0],  (const float*)d_in[1],  (const float*)d_in[2],
        (const float*)d_in[3],  (const float*)d_in[4],  (const float*)d_in[5],
        (const float*)d_in[6],  (const float*)d_in[7],  (const float*)d_in[8],
        (const float*)d_in[9],  (const float*)d_in[10], (const float*)d_in[11],
        (const float*)d_in[12], (const float*)d_in[13], (const float*)d_in[14],
        (float*)d_out);
    out_proj_kernel<<<(B * T / 4) / 256, 256>>>(
        (const float*)d_in[15], (const float*)d_in[16], (float*)d_out);
}

// round 6
// speedup vs baseline: 1.3709x; 1.1845x over previous
#include <cuda_runtime.h>
#include <cuda_bf16.h>

#define FULLMASK 0xffffffffu

namespace {
constexpr int B = 64;
constexpr int T = 32768;
constexpr int R = 16;
}

// Scratch: hidden states for all steps, layout [B][T][R] (contiguous per step).
__device__ float g_hs[(size_t)B * T * R];   // 128 MiB

__device__ __forceinline__ float lrelu(float v) { return v >= 0.f ? v : 0.1f * v; }
__device__ __forceinline__ float tanh_fast(float v) {
    float r;
    asm("tanh.approx.f32 %0, %1;" : "=f"(r) : "f"(v));
    return r;
}

// One warp per sample. Lane (g, j): g = lane>>4, j = lane&15.
// Lane owns hidden unit j; half g sums k = 8g..8g+7 of each gate (split-k),
// halves combined with one shfl_xor(16) per gate.
__global__ void __launch_bounds__(32, 1) hypergru_rnn_kernel(
    const float* __restrict__ x,      // [B,1,T]
    const float* __restrict__ c,      // [B,8]
    const float* __restrict__ h0,     // [1,B,R]
    const float* __restrict__ mlp_w1, const float* __restrict__ mlp_b1,
    const float* __restrict__ mlp_w2, const float* __restrict__ mlp_b2,
    const float* __restrict__ pih_w,  const float* __restrict__ pih_b,
    const float* __restrict__ phh_w,  const float* __restrict__ phh_b,
    const float* __restrict__ pbih_w, const float* __restrict__ pbih_b,
    const float* __restrict__ pbhh_w, const float* __restrict__ pbhh_b,
    float* __restrict__ out)          // only h_last region written here
{
    const int b    = blockIdx.x;
    const int lane = threadIdx.x;
    const int j    = lane & 15;
    const int koff = (lane >> 4) * 8;

    // ---------------- hypernetwork prologue ----------------
    float cv[8];
#pragma unroll
    for (int k = 0; k < 8; ++k) cv[k] = c[b * 8 + k];
    float w1[8];
#pragma unroll
    for (int m = 0; m < 8; ++m) {
        float a = mlp_b1[m];
#pragma unroll
        for (int k = 0; k < 8; ++k) a = fmaf(cv[k], mlp_w1[m * 8 + k], a);
        w1[m] = lrelu(a);
    }
    float w2[8];
#pragma unroll
    for (int m = 0; m < 8; ++m) {
        float a = mlp_b2[m];
#pragma unroll
        for (int k = 0; k < 8; ++k) a = fmaf(w1[k], mlp_w2[m * 8 + k], a);
        w2[m] = lrelu(a);
    }
    auto proj8 = [&](const float* __restrict__ wrow, float bias) -> float {
        float a = bias;
#pragma unroll
        for (int k = 0; k < 8; ++k) a = fmaf(w2[k], wrow[k], a);
        return a;
    };

    // Recurrent weights for this lane's 8 k-terms.
    // r/i weights pre-halved (sigmoid via 0.5*tanh(v/2)+0.5).
    float whr_h[8], whi_h[8], whn[8];
#pragma unroll
    for (int k = 0; k < 8; ++k) {
        const int kk = k + koff;
        whr_h[k] = 0.5f * proj8(phh_w + (size_t)(kk * 48 + j) * 8,      phh_b[kk * 48 + j]);
        whi_h[k] = 0.5f * proj8(phh_w + (size_t)(kk * 48 + 16 + j) * 8, phh_b[kk * 48 + 16 + j]);
        whn[k]   =        proj8(phh_w + (size_t)(kk * 48 + 32 + j) * 8, phh_b[kk * 48 + 32 + j]);
    }
    const float bih_r = proj8(pbih_w + (size_t)j * 8,        pbih_b[j]);
    const float bih_i = proj8(pbih_w + (size_t)(16 + j) * 8, pbih_b[16 + j]);
    const float bhh_r = proj8(pbhh_w + (size_t)j * 8,        pbhh_b[j]);
    const float bhh_i = proj8(pbhh_w + (size_t)(16 + j) * 8, pbhh_b[16 + j]);

    // quarter-scaled seeds: each half seeds 0.25*(input term); xor-combine doubles.
    const float wih_r_q = 0.25f * proj8(pih_w + (size_t)j * 8,        pih_b[j]);
    const float wih_i_q = 0.25f * proj8(pih_w + (size_t)(16 + j) * 8, pih_b[16 + j]);
    const float wih_n   =         proj8(pih_w + (size_t)(32 + j) * 8, pih_b[32 + j]);
    const float cbr_q   = 0.25f * (bih_r + bhh_r);
    const float cbi_q   = 0.25f * (bih_i + bhh_i);
    const float bih_n   = proj8(pbih_w + (size_t)(32 + j) * 8, pbih_b[32 + j]);
    const float bhh_n_h = 0.5f * proj8(pbhh_w + (size_t)(32 + j) * 8, pbhh_b[32 + j]);

    // ---------------- recurrence ----------------
    float h = h0[b * R + j];
    const float* __restrict__ xp = x + (size_t)b * T;
    float* __restrict__ hsp = g_hs + (size_t)b * T * R + j;   // contiguous per step

    float xq = xp[lane];   // 32 timesteps staged per lane
    for (int t0 = 0; t0 < T; t0 += 32) {
        const float xnext = (t0 + 32 < T) ? xp[t0 + 32 + lane] : 0.f;   // prefetch
        for (int tb = 0; tb < 32; tb += 8) {
#pragma unroll
            for (int tt = 0; tt < 8; ++tt) {
                const int ti = tb + tt;
                const float xt = __shfl_sync(FULLMASK, xq, ti, 32);

                // gather this half's 8 h-values
                float hrv[8];
#pragma unroll
                for (int k = 0; k < 8; ++k)
                    hrv[k] = __shfl_sync(FULLMASK, h, k + koff, 16);

                const float seed_r = fmaf(xt, wih_r_q, cbr_q);
                const float seed_i = fmaf(xt, wih_i_q, cbi_q);

                float r0 = fmaf(hrv[0], whr_h[0], seed_r);
                float i0 = fmaf(hrv[0], whi_h[0], seed_i);
                float n0 = fmaf(hrv[0], whn[0],   bhh_n_h);
                float r1 = hrv[4] * whr_h[4];
                float i1 = hrv[4] * whi_h[4];
                float n1 = hrv[4] * whn[4];
#pragma unroll
                for (int k = 1; k < 4; ++k) {
                    r0 = fmaf(hrv[k],     whr_h[k],     r0);
                    r1 = fmaf(hrv[k + 4], whr_h[k + 4], r1);
                    i0 = fmaf(hrv[k],     whi_h[k],     i0);
                    i1 = fmaf(hrv[k + 4], whi_h[k + 4], i1);
                    n0 = fmaf(hrv[k],     whn[k],       n0);
                    n1 = fmaf(hrv[k + 4], whn[k + 4],   n1);
                }
                const float rp = r0 + r1, ip = i0 + i1, np = n0 + n1;
                const float rf = rp + __shfl_xor_sync(FULLMASK, rp, 16);  // 0.5*preact_r
                const float hn = np + __shfl_xor_sync(FULLMASK, np, 16);  // full n hh-sum + bhh_n
                const float iv = ip + __shfl_xor_sync(FULLMASK, ip, 16);  // 0.5*preact_i

                // tanh(rf) first: its result is needed earliest (ng chain)
                const float tr  = tanh_fast(rf);                  // = 2*rg - 1
                const float i_n = fmaf(xt, wih_n, bih_n);
                const float inp = fmaf(0.5f, hn, i_n);            // i_n + 0.5*hn
                const float ng  = tanh_fast(fmaf(tr, 0.5f * hn, inp));
                const float ig  = fmaf(tanh_fast(iv), 0.5f, 0.5f);

                h = fmaf(ig, h - ng, ng);
                if (lane < 16) hsp[(size_t)(t0 + ti) * R] = h;    // 64B contiguous line
            }
        }
        xq = xnext;
    }

    if (lane < 16) out[(size_t)B * T + b * R + j] = h;
}

// Pass 2: y[b,t] = dot(hs[b,t,:], out_w) + out_b  (bandwidth-bound, parallel)
__global__ void __launch_bounds__(256) out_proj_kernel(
    const float* __restrict__ out_w, const float* __restrict__ out_b,
    float* __restrict__ out)
{
    const int idx = blockIdx.x * 256 + threadIdx.x;   // idx = b*T + t
    const float4* __restrict__ hp = reinterpret_cast<const float4*>(g_hs) + (size_t)idx * 4;
    float4 v0 = hp[0], v1 = hp[1], v2 = hp[2], v3 = hp[3];
    const float4* __restrict__ wp = reinterpret_cast<const float4*>(out_w);
    float4 w0 = __ldg(wp), w1 = __ldg(wp + 1), w2 = __ldg(wp + 2), w3 = __ldg(wp + 3);

    float a = __ldg(out_b);
    a = fmaf(v0.x, w0.x, a); a = fmaf(v0.y, w0.y, a); a = fmaf(v0.z, w0.z, a); a = fmaf(v0.w, w0.w, a);
    a = fmaf(v1.x, w1.x, a); a = fmaf(v1.y, w1.y, a); a = fmaf(v1.z, w1.z, a); a = fmaf(v1.w, w1.w, a);
    a = fmaf(v2.x, w2.x, a); a = fmaf(v2.y, w2.y, a); a = fmaf(v2.z, w2.z, a); a = fmaf(v2.w, w2.w, a);
    a = fmaf(v3.x, w3.x, a); a = fmaf(v3.y, w3.y, a); a = fmaf(v3.z, w3.z, a); a = fmaf(v3.w, w3.w, a);
    out[idx] = a;
}

extern "C" void kernel_launch(void* const* d_in, const int* in_sizes, int n_in,
                              void* d_out, int out_size) {
    (void)in_sizes; (void)n_in; (void)out_size;
    hypergru_rnn_kernel<<<B, 32>>>(
        (const float*)d_in[0],  (const float*)d_in[1],  (const float*)d_in[2],
        (const float*)d_in[3],  (const float*)d_in[4],  (const float*)d_in[5],
        (const float*)d_in[6],  (const float*)d_in[7],  (const float*)d_in[8],
        (const float*)d_in[9],  (const float*)d_in[10], (const float*)d_in[11],
        (const float*)d_in[12], (const float*)d_in[13], (const float*)d_in[14],
        (float*)d_out);
    out_proj_kernel<<<(B * T) / 256, 256>>>(
        (const float*)d_in[15], (const float*)d_in[16], (float*)d_out);
}